// round 9
// baseline (speedup 1.0000x reference)
#include <cuda_runtime.h>
#include <float.h>
#include <math.h>

// Problem constants (fixed by the dataset)
#define BSZ      64
#define NH       32
#define KVH      8
#define GROUPS   4          // NH / KVH
#define HD       128
#define BS       16         // paged block size
#define BPS      128        // blocks per sequence
#define MAX_CTX  2048

// Split-KV config
#define CHUNK    256
#define NCHUNK   (MAX_CTX / CHUNK)   // 8
#define NTHREADS 256
#define NWARPS   (NTHREADS / 32)     // 8
#define TILE     32                  // tokens per cp.async tile

#define SCALE 0.08838834764831845f   // 1/sqrt(128)

// Scratch for split-KV partials (static device globals: allocation-free)
__device__ float g_pout[(size_t)BSZ * KVH * NCHUNK * GROUPS * HD]; // 8 MB
__device__ float g_pm[BSZ * KVH * NCHUNK * GROUPS];
__device__ float g_pl[BSZ * KVH * NCHUNK * GROUPS];

#define CP_ASYNC16(sp, gp) \
    asm volatile("cp.async.cg.shared.global [%0], [%1], 16;\n" :: "r"(sp), "l"(gp))
#define CP_COMMIT() asm volatile("cp.async.commit_group;\n" ::: "memory")
#define CP_WAIT1()  asm volatile("cp.async.wait_group 1;\n" ::: "memory")

__global__ __launch_bounds__(NTHREADS, 5)
void attn_chunk_kernel(const float* __restrict__ q,
                       const float* __restrict__ kc,
                       const float* __restrict__ vc,
                       const int*   __restrict__ bt,
                       const int*   __restrict__ lens)
{
    const int bid   = blockIdx.x;
    const int chunk = bid % NCHUNK;
    const int kvh   = (bid / NCHUNK) % KVH;
    const int seq   = bid / (NCHUNK * KVH);
    const int tid   = threadIdx.x;
    const int warp  = tid >> 5;
    const int lane  = tid & 31;

    const int len    = lens[seq];
    const int cstart = chunk * CHUNK;
    if (cstart >= len) return;                 // inactive: reduce kernel won't read it
    const int tend   = min(CHUNK, len - cstart);
    const int ntiles = (tend + TILE - 1) / TILE;

    const int sk    = seq * KVH + kvh;
    const int pbase = (sk * NCHUNK + chunk) * GROUPS;

    // Dynamic smem: [2][TILE*HD] KV ring (32 KB).
    // After the V stream is fully consumed, the SAME region is reused as the
    // PV cross-warp reduce scratch (16 KB needed) — total smem 36.3 KB.
    extern __shared__ float s_kv[];
    float* s_red = s_kv;                           // alias, used post-stream only

    __shared__ int   s_blk[CHUNK / BS];            // 16 ints
    __shared__ float s_sc[GROUPS][CHUNK];          // scores -> probs (4 KB)
    __shared__ float s_m2[2][GROUPS];
    __shared__ float s_l2[2][GROUPS];

    if (tid < CHUNK / BS)
        s_blk[tid] = bt[seq * BPS + (cstart >> 4) + tid];
    // init scores to -inf so tokens beyond tend read as masked in phase 2
    {
        float* p = &s_sc[0][0];
        #pragma unroll
        for (int i = 0; i < GROUPS * CHUNK / NTHREADS; ++i)
            p[tid + i * NTHREADS] = -FLT_MAX;
    }
    __syncthreads();

    const size_t blk_stride = (size_t)KVH * BS * HD;     // floats per paged block
    const float* kbase = kc + (size_t)kvh * BS * HD;
    const float* vbase = vc + (size_t)kvh * BS * HD;

    // cp.async one 32-token tile (16 KB) into s_kv[tile&1]. All 256 threads copy:
    // thread -> token tid>>3, 4x16B chunks at float offsets (tid&7)*4 + 32*k.
    const int cp_tok  = tid >> 3;
    const int cp_part = (tid & 7) * 4;
    unsigned  sb32_0 = (unsigned)__cvta_generic_to_shared(s_kv);
    auto issue_tile = [&](int tile, const float* gbase) {
        if (tile < ntiles) {
            const int gt = tile * TILE + cp_tok;
            const size_t off = (size_t)s_blk[gt >> 4] * blk_stride + (size_t)(gt & 15) * HD;
            const float* gp = gbase + off + cp_part;
            unsigned sp = sb32_0 + ((tile & 1) * (TILE * HD) + cp_tok * HD + cp_part) * 4;
            #pragma unroll
            for (int k = 0; k < 4; ++k)
                CP_ASYNC16(sp + k * 128, gp + k * 32);
        }
        CP_COMMIT();                       // empty group if tile out of range
    };

    // ---------------- Phase 1: scores, K streamed through smem -------------
    issue_tile(0, kbase);
    issue_tile(1, kbase);
    {
        float4 qh[GROUPS];
        #pragma unroll
        for (int g = 0; g < GROUPS; ++g) {
            float4 t = *(const float4*)(q + ((size_t)(seq * NH + kvh * GROUPS + g)) * HD + lane * 4);
            qh[g] = make_float4(t.x * SCALE, t.y * SCALE, t.z * SCALE, t.w * SCALE);
        }
        const int bit0 = lane & 1;
        const int bit1 = lane & 2;

        for (int i = 0; i < ntiles; ++i) {
            CP_WAIT1();                    // tile i resident (tile i+1 may be in flight)
            __syncthreads();
            const float* kb = s_kv + (i & 1) * (TILE * HD);
            #pragma unroll
            for (int j = 0; j < 4; ++j) {
                const int tl = warp * 4 + j;       // token within tile
                const int t  = i * TILE + tl;      // token within chunk
                const float4 k4 = *(const float4*)(kb + tl * HD + lane * 4);

                float p0 = qh[0].x*k4.x + qh[0].y*k4.y + qh[0].z*k4.z + qh[0].w*k4.w;
                float p1 = qh[1].x*k4.x + qh[1].y*k4.y + qh[1].z*k4.z + qh[1].w*k4.w;
                float p2 = qh[2].x*k4.x + qh[2].y*k4.y + qh[2].z*k4.z + qh[2].w*k4.w;
                float p3 = qh[3].x*k4.x + qh[3].y*k4.y + qh[3].z*k4.z + qh[3].w*k4.w;

                // reduce-scatter across lane quads, then butterfly across quads
                float rA = __shfl_xor_sync(0xffffffffu, bit0 ? p0 : p1, 1);
                float x  = (bit0 ? p1 : p0) + rA;
                float rB = __shfl_xor_sync(0xffffffffu, bit0 ? p2 : p3, 1);
                float y  = (bit0 ? p3 : p2) + rB;
                float rC = __shfl_xor_sync(0xffffffffu, bit1 ? x : y, 2);
                float s  = (bit1 ? y : x) + rC;
                s += __shfl_xor_sync(0xffffffffu, s, 4);
                s += __shfl_xor_sync(0xffffffffu, s, 8);
                s += __shfl_xor_sync(0xffffffffu, s, 16);

                const float val = (t < tend) ? s : -FLT_MAX;
                if (lane < GROUPS) s_sc[lane][t] = val;   // lane g holds head g
            }
            __syncthreads();               // buffer i&1 free for refill
            issue_tile(i + 2, kbase);
        }
    }

    // Prologue of the V pipeline (overlaps with softmax below)
    issue_tile(0, vbase);
    issue_tile(1, vbase);

    // ---------------- Phase 2: chunk-local softmax, all 8 warps ------------
    {
        const int g = warp & 3;
        const int h = warp >> 2;
        const int tb = h * (CHUNK / 2);

        float m = -FLT_MAX;
        #pragma unroll
        for (int i = 0; i < CHUNK / 2 / 32; ++i)
            m = fmaxf(m, s_sc[g][tb + i * 32 + lane]);
        #pragma unroll
        for (int off = 16; off > 0; off >>= 1)
            m = fmaxf(m, __shfl_xor_sync(0xffffffffu, m, off));
        if (lane == 0) s_m2[h][g] = m;
        __syncthreads();

        const float M = fmaxf(s_m2[0][g], s_m2[1][g]);
        float l = 0.0f;
        #pragma unroll
        for (int i = 0; i < CHUNK / 2 / 32; ++i) {
            const int t = tb + i * 32 + lane;
            const float s = s_sc[g][t];
            const float p = (s > -0.5f * FLT_MAX) ? __expf(s - M) : 0.0f;
            s_sc[g][t] = p;
            l += p;
        }
        #pragma unroll
        for (int off = 16; off > 0; off >>= 1)
            l += __shfl_xor_sync(0xffffffffu, l, off);
        if (lane == 0) s_l2[h][g] = l;
        __syncthreads();

        if (tid < GROUPS) {
            g_pm[pbase + tid] = fmaxf(s_m2[0][tid], s_m2[1][tid]);
            g_pl[pbase + tid] = s_l2[0][tid] + s_l2[1][tid];
        }
    }

    // ---------------- Phase 3: O_partial = P . V, V streamed through smem --
    {
        float acc[GROUPS][4];
        #pragma unroll
        for (int g = 0; g < GROUPS; ++g) {
            acc[g][0] = 0.f; acc[g][1] = 0.f; acc[g][2] = 0.f; acc[g][3] = 0.f;
        }

        for (int i = 0; i < ntiles; ++i) {
            CP_WAIT1();
            __syncthreads();
            const float* vb = s_kv + (i & 1) * (TILE * HD);
            #pragma unroll
            for (int j = 0; j < 4; ++j) {
                const int tl = warp * 4 + j;
                const int t  = i * TILE + tl;
                const float4 v4 = *(const float4*)(vb + tl * HD + lane * 4);
                #pragma unroll
                for (int g = 0; g < GROUPS; ++g) {
                    const float p = s_sc[g][t];      // 0 for t >= tend
                    acc[g][0] += p * v4.x;
                    acc[g][1] += p * v4.y;
                    acc[g][2] += p * v4.z;
                    acc[g][3] += p * v4.w;
                }
            }
            __syncthreads();
            issue_tile(i + 2, vbase);      // empty commits near/after the tail
        }
        // All real copy groups consumed; ring is dead -> reuse as s_red.

        #pragma unroll
        for (int g = 0; g < GROUPS; ++g) {
            float4* r = (float4*)&s_red[warp * (GROUPS * HD) + g * HD + lane * 4];
            *r = make_float4(acc[g][0], acc[g][1], acc[g][2], acc[g][3]);
        }
    }
    __syncthreads();

    // Cross-warp reduce + write unnormalized partial output
    for (int idx = tid; idx < GROUPS * HD; idx += NTHREADS) {
        float s = 0.0f;
        #pragma unroll
        for (int w = 0; w < NWARPS; ++w) s += s_red[w * (GROUPS * HD) + idx];
        g_pout[(size_t)pbase * HD + idx] = s;
    }
}

// Combine split-KV partials with global log-sum-exp and normalize.
// 128 threads/block: thread = (g, d4) with d4 a float4 column of g_pout.
__global__ __launch_bounds__(GROUPS * HD / 4)
void attn_reduce_kernel(float* __restrict__ out, const int* __restrict__ lens)
{
    const int sk  = blockIdx.x;            // seq*KVH + kvh
    const int seq = sk / KVH;
    const int kvh = sk % KVH;
    const int g   = threadIdx.x >> 5;      // /32
    const int d4  = threadIdx.x & 31;      // float4 column

    const int nact = (lens[seq] + CHUNK - 1) / CHUNK;   // only active chunks written

    float M = -FLT_MAX;
    for (int c = 0; c < nact; ++c)
        M = fmaxf(M, g_pm[(sk * NCHUNK + c) * GROUPS + g]);

    float L = 0.0f;
    float4 o = make_float4(0.f, 0.f, 0.f, 0.f);
    for (int c = 0; c < nact; ++c) {
        const int   pidx = (sk * NCHUNK + c) * GROUPS + g;
        const float f    = __expf(g_pm[pidx] - M);
        L += g_pl[pidx] * f;
        const float4 p = *(const float4*)&g_pout[(size_t)pidx * HD + d4 * 4];
        o.x += p.x * f;  o.y += p.y * f;  o.z += p.z * f;  o.w += p.w * f;
    }
    const float inv = 1.0f / L;
    float4* dst = (float4*)&out[(size_t)seq * (NH * HD) + (kvh * GROUPS + g) * HD + d4 * 4];
    *dst = make_float4(o.x * inv, o.y * inv, o.z * inv, o.w * inv);
}

extern "C" void kernel_launch(void* const* d_in, const int* in_sizes, int n_in,
                              void* d_out, int out_size)
{
    const float* q    = (const float*)d_in[0];
    const float* kc   = (const float*)d_in[1];
    const float* vc   = (const float*)d_in[2];
    const int*   bt   = (const int*)d_in[3];
    const int*   lens = (const int*)d_in[4];
    float* out = (float*)d_out;

    const int dyn_smem = 2 * TILE * HD * sizeof(float);   // 32 KB dynamic
    attn_chunk_kernel<<<BSZ * KVH * NCHUNK, NTHREADS, dyn_smem>>>(q, kc, vc, bt, lens);
    attn_reduce_kernel<<<BSZ * KVH, GROUPS * HD / 4>>>(out, lens);
}

// round 10
// speedup vs baseline: 1.0920x; 1.0920x over previous
#include <cuda_runtime.h>
#include <float.h>
#include <math.h>

// Problem constants (fixed by the dataset)
#define BSZ      64
#define NH       32
#define KVH      8
#define GROUPS   4          // NH / KVH
#define HD       128
#define BS       16         // paged block size
#define BPS      128        // blocks per sequence
#define MAX_CTX  2048

// Split-KV config
#define CHUNK    256
#define NCHUNK   (MAX_CTX / CHUNK)   // 8
#define NTHREADS 256
#define NWARPS   (NTHREADS / 32)     // 8
#define TILE     32                  // tokens per cp.async tile

#define SCALE 0.08838834764831845f   // 1/sqrt(128)

// Scratch for split-KV partials (static device globals: allocation-free)
__device__ float g_pout[(size_t)BSZ * KVH * NCHUNK * GROUPS * HD]; // 8 MB
__device__ float g_pm[BSZ * KVH * NCHUNK * GROUPS];
__device__ float g_pl[BSZ * KVH * NCHUNK * GROUPS];

#define CP_ASYNC16(sp, gp) \
    asm volatile("cp.async.cg.shared.global [%0], [%1], 16;\n" :: "r"(sp), "l"(gp))
#define CP_COMMIT() asm volatile("cp.async.commit_group;\n" ::: "memory")
#define CP_WAIT1()  asm volatile("cp.async.wait_group 1;\n" ::: "memory")

__global__ __launch_bounds__(NTHREADS, 4)
void attn_chunk_kernel(const float* __restrict__ q,
                       const float* __restrict__ kc,
                       const float* __restrict__ vc,
                       const int*   __restrict__ bt,
                       const int*   __restrict__ lens)
{
    const int bid   = blockIdx.x;
    const int chunk = bid % NCHUNK;
    const int kvh   = (bid / NCHUNK) % KVH;
    const int seq   = bid / (NCHUNK * KVH);
    const int tid   = threadIdx.x;
    const int warp  = tid >> 5;
    const int lane  = tid & 31;

    const int len    = lens[seq];
    const int cstart = chunk * CHUNK;
    if (cstart >= len) return;                 // inactive: reduce kernel won't read it
    const int tend   = min(CHUNK, len - cstart);
    const int ntiles = (tend + TILE - 1) / TILE;

    const int sk    = seq * KVH + kvh;
    const int pbase = (sk * NCHUNK + chunk) * GROUPS;

    // Dynamic smem: [2][TILE*HD] KV ring (32 KB).
    // s_red aliases the ring; s_red[w] coincides EXACTLY with warp w's own
    // buffer-0 token slots (w*512..w*512+512), so the post-stream reuse is
    // warp-local and safe without extra cross-warp ordering.
    extern __shared__ float s_kv[];
    float* s_red = s_kv;

    __shared__ int   s_blk[CHUNK / BS];            // 16 ints
    __shared__ float s_sc[GROUPS][CHUNK];          // scores -> probs (4 KB)
    __shared__ float s_m2[2][GROUPS];
    __shared__ float s_l2[2][GROUPS];

    if (tid < CHUNK / BS)
        s_blk[tid] = bt[seq * BPS + (cstart >> 4) + tid];
    // init scores to -inf so tokens beyond tend read as masked in phase 2
    {
        float* p = &s_sc[0][0];
        #pragma unroll
        for (int i = 0; i < GROUPS * CHUNK / NTHREADS; ++i)
            p[tid + i * NTHREADS] = -FLT_MAX;
    }
    __syncthreads();

    const size_t blk_stride = (size_t)KVH * BS * HD;     // floats per paged block
    const float* kbase = kc + (size_t)kvh * BS * HD;
    const float* vbase = vc + (size_t)kvh * BS * HD;

    // cp.async one 32-token tile (16 KB) into s_kv[tile&1].
    // KEY PROPERTY: thread tid copies token tid>>3, so warp w copies exactly
    // tokens w*4..w*4+3 — the very tokens warp w consumes. Streaming loops
    // therefore need only warp-local synchronization.
    const int cp_tok  = tid >> 3;
    const int cp_part = (tid & 7) * 4;
    unsigned  sb32_0 = (unsigned)__cvta_generic_to_shared(s_kv);
    auto issue_tile = [&](int tile, const float* gbase) {
        if (tile < ntiles) {
            const int gt = tile * TILE + cp_tok;
            const size_t off = (size_t)s_blk[gt >> 4] * blk_stride + (size_t)(gt & 15) * HD;
            const float* gp = gbase + off + cp_part;
            unsigned sp = sb32_0 + ((tile & 1) * (TILE * HD) + cp_tok * HD + cp_part) * 4;
            #pragma unroll
            for (int k = 0; k < 4; ++k)
                CP_ASYNC16(sp + k * 128, gp + k * 32);
        }
        CP_COMMIT();                       // empty group if tile out of range
    };

    // ---------------- Phase 1: scores, K streamed through smem (warp-local) ----
    issue_tile(0, kbase);
    issue_tile(1, kbase);
    {
        float4 qh[GROUPS];
        #pragma unroll
        for (int g = 0; g < GROUPS; ++g) {
            float4 t = *(const float4*)(q + ((size_t)(seq * NH + kvh * GROUPS + g)) * HD + lane * 4);
            qh[g] = make_float4(t.x * SCALE, t.y * SCALE, t.z * SCALE, t.w * SCALE);
        }
        const int bit0 = lane & 1;
        const int bit1 = lane & 2;

        for (int i = 0; i < ntiles; ++i) {
            CP_WAIT1();                    // this thread's tile-i copies complete
            __syncwarp();                  // cross-lane visibility within the warp
            const float* kb = s_kv + (i & 1) * (TILE * HD);
            #pragma unroll
            for (int j = 0; j < 4; ++j) {
                const int tl = warp * 4 + j;       // warp-owned token within tile
                const int t  = i * TILE + tl;      // token within chunk
                const float4 k4 = *(const float4*)(kb + tl * HD + lane * 4);

                float p0 = qh[0].x*k4.x + qh[0].y*k4.y + qh[0].z*k4.z + qh[0].w*k4.w;
                float p1 = qh[1].x*k4.x + qh[1].y*k4.y + qh[1].z*k4.z + qh[1].w*k4.w;
                float p2 = qh[2].x*k4.x + qh[2].y*k4.y + qh[2].z*k4.z + qh[2].w*k4.w;
                float p3 = qh[3].x*k4.x + qh[3].y*k4.y + qh[3].z*k4.z + qh[3].w*k4.w;

                // reduce-scatter across lane quads, then butterfly across quads
                float rA = __shfl_xor_sync(0xffffffffu, bit0 ? p0 : p1, 1);
                float x  = (bit0 ? p1 : p0) + rA;
                float rB = __shfl_xor_sync(0xffffffffu, bit0 ? p2 : p3, 1);
                float y  = (bit0 ? p3 : p2) + rB;
                float rC = __shfl_xor_sync(0xffffffffu, bit1 ? x : y, 2);
                float s  = (bit1 ? y : x) + rC;
                s += __shfl_xor_sync(0xffffffffu, s, 4);
                s += __shfl_xor_sync(0xffffffffu, s, 8);
                s += __shfl_xor_sync(0xffffffffu, s, 16);

                const float val = (t < tend) ? s : -FLT_MAX;
                if (lane < GROUPS) s_sc[lane][t] = val;   // lane g holds head g
            }
            __syncwarp();                  // all lanes done reading warp's slots
            issue_tile(i + 2, kbase);      // refill overwrites only our tokens
        }
    }

    // V pipeline prologue (warp-owned slots; overlaps the softmax below)
    issue_tile(0, vbase);
    issue_tile(1, vbase);

    __syncthreads();                       // s_sc complete across all warps

    // ---------------- Phase 2: chunk-local softmax, all 8 warps ------------
    {
        const int g = warp & 3;
        const int h = warp >> 2;
        const int tb = h * (CHUNK / 2);

        float m = -FLT_MAX;
        #pragma unroll
        for (int i = 0; i < CHUNK / 2 / 32; ++i)
            m = fmaxf(m, s_sc[g][tb + i * 32 + lane]);
        #pragma unroll
        for (int off = 16; off > 0; off >>= 1)
            m = fmaxf(m, __shfl_xor_sync(0xffffffffu, m, off));
        if (lane == 0) s_m2[h][g] = m;
        __syncthreads();

        const float M = fmaxf(s_m2[0][g], s_m2[1][g]);
        float l = 0.0f;
        #pragma unroll
        for (int i = 0; i < CHUNK / 2 / 32; ++i) {
            const int t = tb + i * 32 + lane;
            const float s = s_sc[g][t];
            const float p = (s > -0.5f * FLT_MAX) ? __expf(s - M) : 0.0f;
            s_sc[g][t] = p;
            l += p;
        }
        #pragma unroll
        for (int off = 16; off > 0; off >>= 1)
            l += __shfl_xor_sync(0xffffffffu, l, off);
        if (lane == 0) s_l2[h][g] = l;
        __syncthreads();

        if (tid < GROUPS) {
            g_pm[pbase + tid] = fmaxf(s_m2[0][tid], s_m2[1][tid]);
            g_pl[pbase + tid] = s_l2[0][tid] + s_l2[1][tid];
        }
    }

    // ---------------- Phase 3: O_partial = P . V (warp-local streaming) -----
    {
        float acc[GROUPS][4];
        #pragma unroll
        for (int g = 0; g < GROUPS; ++g) {
            acc[g][0] = 0.f; acc[g][1] = 0.f; acc[g][2] = 0.f; acc[g][3] = 0.f;
        }

        for (int i = 0; i < ntiles; ++i) {
            CP_WAIT1();
            __syncwarp();
            const float* vb = s_kv + (i & 1) * (TILE * HD);
            #pragma unroll
            for (int j = 0; j < 4; ++j) {
                const int tl = warp * 4 + j;
                const int t  = i * TILE + tl;
                const float4 v4 = *(const float4*)(vb + tl * HD + lane * 4);
                #pragma unroll
                for (int g = 0; g < GROUPS; ++g) {
                    const float p = s_sc[g][t];      // 0 for t >= tend
                    acc[g][0] += p * v4.x;
                    acc[g][1] += p * v4.y;
                    acc[g][2] += p * v4.z;
                    acc[g][3] += p * v4.w;
                }
            }
            __syncwarp();
            issue_tile(i + 2, vbase);      // empty commits near/after the tail
        }
        __syncwarp();                      // lanes done reading warp's buffer-0 slots

        // Ring dead for this warp; s_red[warp] == our own buffer-0 region.
        #pragma unroll
        for (int g = 0; g < GROUPS; ++g) {
            float4* r = (float4*)&s_red[warp * (GROUPS * HD) + g * HD + lane * 4];
            *r = make_float4(acc[g][0], acc[g][1], acc[g][2], acc[g][3]);
        }
    }
    __syncthreads();

    // Cross-warp reduce + write unnormalized partial output
    for (int idx = tid; idx < GROUPS * HD; idx += NTHREADS) {
        float s = 0.0f;
        #pragma unroll
        for (int w = 0; w < NWARPS; ++w) s += s_red[w * (GROUPS * HD) + idx];
        g_pout[(size_t)pbase * HD + idx] = s;
    }
}

// Combine split-KV partials with global log-sum-exp and normalize.
__global__ __launch_bounds__(GROUPS * HD)
void attn_reduce_kernel(float* __restrict__ out, const int* __restrict__ lens)
{
    const int sk  = blockIdx.x;            // seq*KVH + kvh
    const int seq = sk / KVH;
    const int kvh = sk % KVH;
    const int g   = threadIdx.x / HD;
    const int d   = threadIdx.x % HD;

    const int nact = (lens[seq] + CHUNK - 1) / CHUNK;   // only active chunks written

    float M = -FLT_MAX;
    #pragma unroll
    for (int c = 0; c < NCHUNK; ++c) {
        const float mc = (c < nact) ? g_pm[(sk * NCHUNK + c) * GROUPS + g] : -FLT_MAX;
        M = fmaxf(M, mc);
    }

    float L = 0.0f, o = 0.0f;
    #pragma unroll
    for (int c = 0; c < NCHUNK; ++c) {
        if (c < nact) {
            const int   pidx = (sk * NCHUNK + c) * GROUPS + g;
            const float f    = __expf(g_pm[pidx] - M);
            L += g_pl[pidx] * f;
            o += g_pout[(size_t)pidx * HD + d] * f;
        }
    }
    out[(size_t)seq * (NH * HD) + (kvh * GROUPS + g) * HD + d] = o / L;
}

extern "C" void kernel_launch(void* const* d_in, const int* in_sizes, int n_in,
                              void* d_out, int out_size)
{
    const float* q    = (const float*)d_in[0];
    const float* kc   = (const float*)d_in[1];
    const float* vc   = (const float*)d_in[2];
    const int*   bt   = (const int*)d_in[3];
    const int*   lens = (const int*)d_in[4];
    float* out = (float*)d_out;

    const int dyn_smem = 2 * TILE * HD * sizeof(float);   // 32 KB dynamic
    attn_chunk_kernel<<<BSZ * KVH * NCHUNK, NTHREADS, dyn_smem>>>(q, kc, vc, bt, lens);
    attn_reduce_kernel<<<BSZ * KVH, GROUPS * HD>>>(out, lens);
}